// round 16
// baseline (speedup 1.0000x reference)
#include <cuda_runtime.h>
#include <cuda_bf16.h>
#include <cstdint>

typedef unsigned long long u64;
typedef uint32_t u32;

#define DIM    64
#define KCODE  1024
#define OFF_Q    1
#define OFF_PERP 4194305
#define OFF_ENC  4194306
#define EPS    6e-4f

// -------- device scratch (static; no cudaMalloc) --------
// tile-ready B (bf16 hi): [chunk8][tile16][s4][g8][t4_4][2 u32] = [bh0,bh1], b=-2e
__device__ __align__(16) u32 g_wbh[KCODE * 32];
__device__ float g_enorm[KCODE];
__device__ float g_partial[512];
__device__ int   g_counts[KCODE];

// m16n8k16 bf16 MMA, f32 accum (sm_80 ISA -> valid on bare sm_103, tensor pipe)
__device__ __forceinline__ void mma16816(float* c, const u32* a, u32 b0, u32 b1) {
    asm volatile(
        "mma.sync.aligned.m16n8k16.row.col.f32.bf16.bf16.f32 "
        "{%0,%1,%2,%3}, {%4,%5,%6,%7}, {%8,%9}, {%0,%1,%2,%3};"
        : "+f"(c[0]), "+f"(c[1]), "+f"(c[2]), "+f"(c[3])
        : "r"(a[0]), "r"(a[1]), "r"(a[2]), "r"(a[3]), "r"(b0), "r"(b1));
}

__device__ __forceinline__ u64 packdk(float d, int k) {
    return ((u64)__float_as_uint(d) << 32) | (u32)k;
}
__device__ __forceinline__ u32 pkbf(float a, float b) {
    return (u32)__bfloat16_as_ushort(__float2bfloat16(a))
         | ((u32)__bfloat16_as_ushort(__float2bfloat16(b)) << 16);
}

// -------- prep: enorm (R3 order), counts, tile-ready bf16 pack of -2w --------
__global__ void vq_prep(const float* __restrict__ w) {
    const int k = blockIdx.x * 32 + threadIdx.x;   // 32 blocks x 32 thr: 32 SMs
    if (k >= KCODE) return;
    const float* e = w + (size_t)k * DIM;
    float s0 = 0.f, s1 = 0.f, s2 = 0.f, s3 = 0.f;
#pragma unroll
    for (int d = 0; d < DIM; d += 4) {
        s0 = fmaf(e[d],     e[d],     s0);
        s1 = fmaf(e[d + 1], e[d + 1], s1);
        s2 = fmaf(e[d + 2], e[d + 2], s2);
        s3 = fmaf(e[d + 3], e[d + 3], s3);
    }
    g_enorm[k]  = (s0 + s1) + (s2 + s3);
    g_counts[k] = 0;

    u32 ph[32];
#pragma unroll
    for (int j = 0; j < 32; j++)
        ph[j] = pkbf(-2.0f * e[2 * j], -2.0f * e[2 * j + 1]);
#pragma unroll
    for (int s = 0; s < 4; s++)
#pragma unroll
        for (int t4 = 0; t4 < 4; t4++) {
            const uint2 val = make_uint2(ph[8 * s + t4], ph[8 * s + t4 + 4]);
            const size_t off = (size_t)(k >> 7) * 4096
                             + (((((k >> 3) & 15) * 4 + s) * 8 + (k & 7)) * 8) + t4 * 2;
            *(uint2*)(g_wbh + off) = val;
        }
}

// exact reference distance (R3-proven bitwise sequence); x via strided pointer
__device__ __forceinline__ float exact_dist(const float* __restrict__ xin,
                                            const float* __restrict__ w,
                                            int k, float xnorm, float en) {
    const float* e = w + (size_t)k * DIM;
    float a0 = 0.f, a1 = 0.f, a2 = 0.f, a3 = 0.f;
#pragma unroll
    for (int d = 0; d < DIM; d += 4) {
        a0 = fmaf(xin[(size_t)d * 1024],       e[d],     a0);
        a1 = fmaf(xin[(size_t)(d + 1) * 1024], e[d + 1], a1);
        a2 = fmaf(xin[(size_t)(d + 2) * 1024], e[d + 2], a2);
        a3 = fmaf(xin[(size_t)(d + 3) * 1024], e[d + 3], a3);
    }
    const float dot = (a0 + a1) + (a2 + a3);
    const float t   = xnorm + en;
    return fmaf(-2.0f, dot, t);
}

// -------- main: 9-step bf16 HMMA sweep (warm-up + running threshold) --------
// Tile body is byte-identical to the R11/R15-proven compilation. Do not reorganize.
__global__ void __launch_bounds__(256, 2)
vq_mma(const float* __restrict__ x, const float* __restrict__ w, float* __restrict__ out) {
    extern __shared__ u32 smem[];
    u32*   sA    = smem;                       // 128 x 68 : [xh 32 | xl 32]
    u32*   sB    = smem + 8704;                // 4096 : tile-ready bh chunk
    float* sEN   = (float*)(smem + 12800);     // 1024 f32 enorm (exact recheck)
    float* sXN   = (float*)(smem + 13824);     // 128
    int*   sBest = (int*)(smem + 13952);       // 128
    float* sRed  = (float*)(smem + 14080);     // 128
    u32*   sCand = smem + 14208;               // 256 x 16 candidate slots
    // total 18304 u32 = 73216 B

    const int tid  = threadIdx.x;
    const int lane = tid & 31, warp = tid >> 5;
    const int g = lane >> 2, t4 = lane & 3;
    const int blk = blockIdx.x;

    // ---- early: zero-fill this block's one-hot region (overlaps GEMM DRAM-idle) ----
    {
        float2* zb = ((float2*)(out + OFF_ENC)) + (size_t)blk * 65536;
        const float2 z = make_float2(0.f, 0.f);
#pragma unroll 4
        for (int i = tid; i < 65536; i += 256) zb[i] = z;
    }

    // ---- stage: threads 0-127 pack x hi/lo + xnorm; 128-255 copy enorm ----
    if (tid < 128) {
        const int v = blk * 128 + tid;
        const float* xin = x + (size_t)(v >> 10) * 65536 + (v & 1023);
        float s0 = 0.f, s1 = 0.f, s2 = 0.f, s3 = 0.f;
#pragma unroll
        for (int j = 0; j < 32; j++) {
            const float x0 = xin[(size_t)(2 * j) * 1024];
            const float x1 = xin[(size_t)(2 * j + 1) * 1024];
            if (j & 1) { s2 = fmaf(x0, x0, s2); s3 = fmaf(x1, x1, s3); }
            else       { s0 = fmaf(x0, x0, s0); s1 = fmaf(x1, x1, s1); }
            const float h0 = __bfloat162float(__float2bfloat16(x0));
            const float h1 = __bfloat162float(__float2bfloat16(x1));
            sA[tid * 68 + j]      = pkbf(x0, x1);
            sA[tid * 68 + 32 + j] = pkbf(x0 - h0, x1 - h1);
        }
        sXN[tid] = (s0 + s1) + (s2 + s3);      // bitwise == R3 xnorm order
    } else {
        for (int i = tid - 128; i < KCODE; i += 128) sEN[i] = g_enorm[i];
    }
    __syncthreads();

    // ---- A fragments: rows r0=warp*16+g, r1=r0+8 ----
    const int r0 = warp * 16 + g, r1 = r0 + 8;
    u32 a[2][4][4];
#pragma unroll
    for (int seg = 0; seg < 2; seg++)
#pragma unroll
        for (int s = 0; s < 4; s++) {
            const int o = seg * 32 + s * 8 + t4;
            a[seg][s][0] = sA[r0 * 68 + o];
            a[seg][s][1] = sA[r1 * 68 + o];
            a[seg][s][2] = sA[r0 * 68 + o + 4];
            a[seg][s][3] = sA[r1 * 68 + o + 4];
        }
    const float xn0 = sXN[r0], xn1 = sXN[r1];

    const float INF = __int_as_float(0x7f800000);
    float m0 = INF, m1 = INF;
    float thr0 = INF, thr1 = INF;
    u32* myCand = sCand + tid * 16;
    int  cnt = 0;

    // ---- 9-step sweep: step0 = chunk0 min-only (warm-up); steps1-7 = chunks1-7
    //      with running-threshold appends; step8 = chunk0 with converged threshold.
    //      Invariant: thr_local >= final_min + EPS at all times -> candidate superset.
#pragma unroll 1
    for (int step = 0; step < 9; step++) {
        const int  ch     = (step == 0) ? 0 : (step & 7);   // 0,1..7,0
        const bool append = (step != 0);
        __syncthreads();
        const uint4* gsrc = (const uint4*)(g_wbh + (size_t)ch * 4096);
        uint4* gdst = (uint4*)sB;
        for (int i4 = tid; i4 < 1024; i4 += 256) gdst[i4] = gsrc[i4];
        __syncthreads();

#pragma unroll 4
        for (int tile = 0; tile < 16; tile++) {
            const u32* bp = sB + tile * 256 + g * 8 + t4 * 2;
            const uint2 b0 = *(const uint2*)(bp);
            const uint2 b1 = *(const uint2*)(bp + 64);
            const uint2 b2 = *(const uint2*)(bp + 128);
            const uint2 b3 = *(const uint2*)(bp + 192);

            // two independent accumulator chains (depth 4) -> latency hidden
            float cA[4] = {0.f, 0.f, 0.f, 0.f};
            float cB[4] = {0.f, 0.f, 0.f, 0.f};
            mma16816(cA, a[0][0], b0.x, b0.y);   // xh s0
            mma16816(cB, a[0][2], b2.x, b2.y);   // xh s2
            mma16816(cA, a[0][1], b1.x, b1.y);   // xh s1
            mma16816(cB, a[0][3], b3.x, b3.y);   // xh s3
            mma16816(cA, a[1][0], b0.x, b0.y);   // xl s0
            mma16816(cB, a[1][2], b2.x, b2.y);   // xl s2
            mma16816(cA, a[1][1], b1.x, b1.y);   // xl s1
            mma16816(cB, a[1][3], b3.x, b3.y);   // xl s3

            const float c0 = cA[0] + cB[0];
            const float c1 = cA[1] + cB[1];
            const float c2 = cA[2] + cB[2];
            const float c3 = cA[3] + cB[3];

            const float pm0 = fminf(c0, c1);
            const float pm1 = fminf(c2, c3);
            if (append && (pm0 <= thr0 || pm1 <= thr1)) {  // rare after warm-up
                const int k0 = ch * 128 + tile * 8 + 2 * t4;
                if (c0 <= thr0) { myCand[cnt & 15] = (u32)(k0 << 1);             cnt++; }
                if (c1 <= thr0) { myCand[cnt & 15] = (u32)((k0 + 1) << 1);       cnt++; }
                if (c2 <= thr1) { myCand[cnt & 15] = (u32)((k0 << 1) | 1);       cnt++; }
                if (c3 <= thr1) { myCand[cnt & 15] = (u32)(((k0 + 1) << 1) | 1); cnt++; }
            }
            m0 = fminf(m0, pm0);
            m1 = fminf(m1, pm1);
            thr0 = m0 + EPS;
            thr1 = m1 + EPS;
        }
    }

    // ---- exact resolution of candidates (bitwise reference sequence) ----
    const int vr0 = blk * 128 + r0, vr1 = blk * 128 + r1;
    const float* xin0 = x + (size_t)(vr0 >> 10) * 65536 + (vr0 & 1023);
    const float* xin1 = x + (size_t)(vr1 >> 10) * 65536 + (vr1 & 1023);
    u64 best0 = ~0ull, best1 = ~0ull;
    if (cnt <= 16) {
        for (int i = 0; i < cnt; i++) {
            const u32 ent = myCand[i];
            const int k = (int)(ent >> 1);
            if (ent & 1) {
                const u64 p = packdk(exact_dist(xin1, w, k, xn1, sEN[k]), k);
                if (p < best1) best1 = p;
            } else {
                const u64 p = packdk(exact_dist(xin0, w, k, xn0, sEN[k]), k);
                if (p < best0) best0 = p;
            }
        }
    } else {   // overflow (P < 1e-5/thread): exact scan of this thread's subset
        for (int i = 0; i < 128; i++)
#pragma unroll
            for (int i2 = 0; i2 < 2; i2++) {
                const int k = i * 8 + 2 * t4 + i2;
                const u64 p0 = packdk(exact_dist(xin0, w, k, xn0, sEN[k]), k);
                const u64 p1 = packdk(exact_dist(xin1, w, k, xn1, sEN[k]), k);
                if (p0 < best0) best0 = p0;
                if (p1 < best1) best1 = p1;
            }
    }
#pragma unroll
    for (int m = 1; m <= 2; m <<= 1) {
        const u64 o0 = __shfl_xor_sync(0xffffffffu, best0, m);
        const u64 o1 = __shfl_xor_sync(0xffffffffu, best1, m);
        if (o0 < best0) best0 = o0;
        if (o1 < best1) best1 = o1;
    }
    if (t4 == 0) {
        sBest[r0] = (int)(best0 & 0xffffffffu);
        sBest[r1] = (int)(best1 & 0xffffffffu);
    }
    __syncthreads();

    // ---- fused epilogue: STE quantized + loss + counts + one-hot '1' fixup ----
    if (tid < 128) {
        const int v  = blk * 128 + tid;
        const int kk = sBest[tid];
        const float* eb  = w + (size_t)kk * DIM;
        const float* xin = x + (size_t)(v >> 10) * 65536 + (v & 1023);
        float*       q   = out + OFF_Q + (size_t)(v >> 10) * 65536 + (v & 1023);
        float diff2 = 0.f;
#pragma unroll
        for (int d = 0; d < DIM; d++) {
            const float xv = xin[(size_t)d * 1024];
            const float df = __fsub_rn(eb[d], xv);
            diff2 = fmaf(df, df, diff2);
            q[(size_t)d * 1024] = __fadd_rn(xv, df);
        }
        atomicAdd(&g_counts[kk], 1);
        sRed[tid] = diff2;
        out[OFF_ENC + (size_t)v * 1024 + kk] = 1.0f;   // zeros streamed earlier
    }
    __syncthreads();
#pragma unroll
    for (int s = 64; s > 0; s >>= 1) {
        if (tid < s) sRed[tid] += sRed[tid + s];
        __syncthreads();
    }
    if (tid == 0) g_partial[blk] = sRed[0];
}

// -------- finalize: loss scalar + perplexity --------
__global__ void vq_finalize(float* __restrict__ out) {
    __shared__ float sh[512];
    const int t = threadIdx.x;

    sh[t] = g_partial[t];
    __syncthreads();
#pragma unroll
    for (int s = 256; s > 0; s >>= 1) {
        if (t < s) sh[t] += sh[t + s];
        __syncthreads();
    }
    if (t == 0) out[0] = 0.25f * sh[0] / 4194304.0f;
    __syncthreads();

    float term = 0.f;
#pragma unroll
    for (int k = t; k < KCODE; k += 512) {
        const float p = (float)g_counts[k] * (1.0f / 65536.0f);
        term += p * logf(p + 1e-10f);
    }
    sh[t] = term;
    __syncthreads();
#pragma unroll
    for (int s = 256; s > 0; s >>= 1) {
        if (t < s) sh[t] += sh[t + s];
        __syncthreads();
    }
    if (t == 0) out[OFF_PERP] = expf(-sh[0]);
}

extern "C" void kernel_launch(void* const* d_in, const int* in_sizes, int n_in,
                              void* d_out, int out_size) {
    const float* x = (const float*)d_in[0];   // [64,64,32,32] f32 NCHW
    const float* w = (const float*)d_in[1];   // [1024,64] f32
    float* out = (float*)d_out;

    cudaFuncSetAttribute(vq_mma, cudaFuncAttributeMaxDynamicSharedMemorySize, 73216);

    vq_prep<<<32, 32>>>(w);
    vq_mma<<<512, 256, 73216>>>(x, w, out);
    vq_finalize<<<1, 512>>>(out);
}

// round 17
// speedup vs baseline: 2.6288x; 2.6288x over previous
#include <cuda_runtime.h>
#include <cuda_bf16.h>
#include <cstdint>

typedef unsigned long long u64;
typedef uint32_t u32;

#define DIM    64
#define KCODE  1024
#define OFF_Q    1
#define OFF_PERP 4194305
#define OFF_ENC  4194306
#define EPS    6e-4f

// -------- device scratch (static; no cudaMalloc) --------
// tile-ready B (bf16 hi): [chunk8][tile16][s4][g8][t4_4][2 u32] = [bh0,bh1], b=-2e
__device__ __align__(16) u32 g_wbh[KCODE * 32];
__device__ float g_enorm[KCODE];
__device__ float g_partial[512];
__device__ int   g_counts[KCODE];

// m16n8k16 bf16 MMA, f32 accum (sm_80 ISA -> valid on bare sm_103, tensor pipe)
__device__ __forceinline__ void mma16816(float* c, const u32* a, u32 b0, u32 b1) {
    asm volatile(
        "mma.sync.aligned.m16n8k16.row.col.f32.bf16.bf16.f32 "
        "{%0,%1,%2,%3}, {%4,%5,%6,%7}, {%8,%9}, {%0,%1,%2,%3};"
        : "+f"(c[0]), "+f"(c[1]), "+f"(c[2]), "+f"(c[3])
        : "r"(a[0]), "r"(a[1]), "r"(a[2]), "r"(a[3]), "r"(b0), "r"(b1));
}

__device__ __forceinline__ u64 packdk(float d, int k) {
    return ((u64)__float_as_uint(d) << 32) | (u32)k;
}
__device__ __forceinline__ u32 pkbf(float a, float b) {
    return (u32)__bfloat16_as_ushort(__float2bfloat16(a))
         | ((u32)__bfloat16_as_ushort(__float2bfloat16(b)) << 16);
}

// -------- prep: enorm (R3 order), counts, tile-ready bf16 pack of -2w (hi/lo) --------
__global__ void vq_prep(const float* __restrict__ w) {
    const int k = blockIdx.x * 32 + threadIdx.x;   // 32 blocks: spreads across 32 SMs
    if (k >= KCODE) return;
    const float* e = w + (size_t)k * DIM;
    float s0 = 0.f, s1 = 0.f, s2 = 0.f, s3 = 0.f;
#pragma unroll
    for (int d = 0; d < DIM; d += 4) {
        s0 = fmaf(e[d],     e[d],     s0);
        s1 = fmaf(e[d + 1], e[d + 1], s1);
        s2 = fmaf(e[d + 2], e[d + 2], s2);
        s3 = fmaf(e[d + 3], e[d + 3], s3);
    }
    g_enorm[k]  = (s0 + s1) + (s2 + s3);
    g_counts[k] = 0;

    u32 ph[32];
#pragma unroll
    for (int j = 0; j < 32; j++)
        ph[j] = pkbf(-2.0f * e[2 * j], -2.0f * e[2 * j + 1]);
#pragma unroll
    for (int s = 0; s < 4; s++)
#pragma unroll
        for (int t4 = 0; t4 < 4; t4++) {
            const uint2 val = make_uint2(ph[8 * s + t4], ph[8 * s + t4 + 4]);
            const size_t off = (size_t)(k >> 7) * 4096
                             + (((((k >> 3) & 15) * 4 + s) * 8 + (k & 7)) * 8) + t4 * 2;
            *(uint2*)(g_wbh + off) = val;
        }
}

// exact reference distance (R3-proven bitwise sequence); x via strided pointer
__device__ __forceinline__ float exact_dist(const float* __restrict__ xin,
                                            const float* __restrict__ w,
                                            int k, float xnorm, float en) {
    const float* e = w + (size_t)k * DIM;
    float a0 = 0.f, a1 = 0.f, a2 = 0.f, a3 = 0.f;
#pragma unroll
    for (int d = 0; d < DIM; d += 4) {
        a0 = fmaf(xin[(size_t)d * 1024],       e[d],     a0);
        a1 = fmaf(xin[(size_t)(d + 1) * 1024], e[d + 1], a1);
        a2 = fmaf(xin[(size_t)(d + 2) * 1024], e[d + 2], a2);
        a3 = fmaf(xin[(size_t)(d + 3) * 1024], e[d + 3], a3);
    }
    const float dot = (a0 + a1) + (a2 + a3);
    const float t   = xnorm + en;
    return fmaf(-2.0f, dot, t);
}

// -------- main: two-pass bf16 HMMA (4 indep chains) + threshold + exact argmin --------
// R11/R15-proven configuration: byte-identical. DO NOT REORGANIZE — five rounds of
// evidence show any textual change to this loop flips ptxas into a 1.7-2.7x slower
// compilation (R12/R13/R14/R16).
__global__ void __launch_bounds__(256, 2)
vq_mma(const float* __restrict__ x, const float* __restrict__ w, float* __restrict__ out) {
    extern __shared__ u32 smem[];
    u32*   sA    = smem;                       // 128 x 68 : [xh 32 | xl 32]
    u32*   sB    = smem + 8704;                // 4096 : tile-ready bh chunk
    float* sEN   = (float*)(smem + 12800);     // 1024 f32 enorm (exact recheck)
    float* sXN   = (float*)(smem + 13824);     // 128
    int*   sBest = (int*)(smem + 13952);       // 128
    float* sRed  = (float*)(smem + 14080);     // 128
    u32*   sCand = smem + 14208;               // 256 x 8 candidate slots
    // total 16256 u32 = 65024 B

    const int tid  = threadIdx.x;
    const int lane = tid & 31, warp = tid >> 5;
    const int g = lane >> 2, t4 = lane & 3;
    const int blk = blockIdx.x;

    // ---- early: zero-fill this block's one-hot region (overlaps GEMM DRAM-idle) ----
    {
        float2* zb = ((float2*)(out + OFF_ENC)) + (size_t)blk * 65536;
        const float2 z = make_float2(0.f, 0.f);
#pragma unroll 4
        for (int i = tid; i < 65536; i += 256) zb[i] = z;
    }

    // ---- stage: threads 0-127 pack x hi/lo + xnorm; 128-255 copy enorm ----
    if (tid < 128) {
        const int v = blk * 128 + tid;
        const float* xin = x + (size_t)(v >> 10) * 65536 + (v & 1023);
        float s0 = 0.f, s1 = 0.f, s2 = 0.f, s3 = 0.f;
#pragma unroll
        for (int j = 0; j < 32; j++) {
            const float x0 = xin[(size_t)(2 * j) * 1024];
            const float x1 = xin[(size_t)(2 * j + 1) * 1024];
            if (j & 1) { s2 = fmaf(x0, x0, s2); s3 = fmaf(x1, x1, s3); }
            else       { s0 = fmaf(x0, x0, s0); s1 = fmaf(x1, x1, s1); }
            const float h0 = __bfloat162float(__float2bfloat16(x0));
            const float h1 = __bfloat162float(__float2bfloat16(x1));
            sA[tid * 68 + j]      = pkbf(x0, x1);
            sA[tid * 68 + 32 + j] = pkbf(x0 - h0, x1 - h1);
        }
        sXN[tid] = (s0 + s1) + (s2 + s3);      // bitwise == R3 xnorm order
    } else {
        for (int i = tid - 128; i < KCODE; i += 128) sEN[i] = g_enorm[i];
    }
    __syncthreads();

    // ---- A fragments: rows r0=warp*16+g, r1=r0+8 ----
    const int r0 = warp * 16 + g, r1 = r0 + 8;
    u32 a[2][4][4];
#pragma unroll
    for (int seg = 0; seg < 2; seg++)
#pragma unroll
        for (int s = 0; s < 4; s++) {
            const int o = seg * 32 + s * 8 + t4;
            a[seg][s][0] = sA[r0 * 68 + o];
            a[seg][s][1] = sA[r1 * 68 + o];
            a[seg][s][2] = sA[r0 * 68 + o + 4];
            a[seg][s][3] = sA[r1 * 68 + o + 4];
        }
    const float xn0 = sXN[r0], xn1 = sXN[r1];

    const float INF = __int_as_float(0x7f800000);
    float m0 = INF, m1 = INF;
    float thr0 = INF, thr1 = INF;
    u32* myCand = sCand + tid * 8;
    int  cnt = 0;

    // ---- two passes over the full codebook ----
#pragma unroll 1
    for (int pass = 0; pass < 2; pass++) {
#pragma unroll 1
        for (int ch = 0; ch < 8; ch++) {
            __syncthreads();
            const uint4* gsrc = (const uint4*)(g_wbh + (size_t)ch * 4096);
            uint4* gdst = (uint4*)sB;
            for (int i4 = tid; i4 < 1024; i4 += 256) gdst[i4] = gsrc[i4];
            __syncthreads();

#pragma unroll 4
            for (int tile = 0; tile < 16; tile++) {
                const u32* bp = sB + tile * 256 + g * 8 + t4 * 2;
                const uint2 b0 = *(const uint2*)(bp);
                const uint2 b1 = *(const uint2*)(bp + 64);
                const uint2 b2 = *(const uint2*)(bp + 128);
                const uint2 b3 = *(const uint2*)(bp + 192);

                // two independent accumulator chains (depth 4) -> latency hidden
                float cA[4] = {0.f, 0.f, 0.f, 0.f};
                float cB[4] = {0.f, 0.f, 0.f, 0.f};
                mma16816(cA, a[0][0], b0.x, b0.y);   // xh s0
                mma16816(cB, a[0][2], b2.x, b2.y);   // xh s2
                mma16816(cA, a[0][1], b1.x, b1.y);   // xh s1
                mma16816(cB, a[0][3], b3.x, b3.y);   // xh s3
                mma16816(cA, a[1][0], b0.x, b0.y);   // xl s0
                mma16816(cB, a[1][2], b2.x, b2.y);   // xl s2
                mma16816(cA, a[1][1], b1.x, b1.y);   // xl s1
                mma16816(cB, a[1][3], b3.x, b3.y);   // xl s3

                const float c0 = cA[0] + cB[0];
                const float c1 = cA[1] + cB[1];
                const float c2 = cA[2] + cB[2];
                const float c3 = cA[3] + cB[3];

                const float pm0 = fminf(c0, c1);
                const float pm1 = fminf(c2, c3);
                if (pass == 0) {
                    m0 = fminf(m0, pm0);
                    m1 = fminf(m1, pm1);
                } else if (pm0 <= thr0 || pm1 <= thr1) {   // rare: append candidates
                    const int k0 = ch * 128 + tile * 8 + 2 * t4;
                    if (c0 <= thr0) { myCand[cnt & 7] = (u32)(k0 << 1);             cnt++; }
                    if (c1 <= thr0) { myCand[cnt & 7] = (u32)((k0 + 1) << 1);       cnt++; }
                    if (c2 <= thr1) { myCand[cnt & 7] = (u32)((k0 << 1) | 1);       cnt++; }
                    if (c3 <= thr1) { myCand[cnt & 7] = (u32)(((k0 + 1) << 1) | 1); cnt++; }
                }
            }
        }
        if (pass == 0) {
#pragma unroll
            for (int m = 1; m <= 2; m <<= 1) {
                m0 = fminf(m0, __shfl_xor_sync(0xffffffffu, m0, m));
                m1 = fminf(m1, __shfl_xor_sync(0xffffffffu, m1, m));
            }
            thr0 = m0 + EPS;
            thr1 = m1 + EPS;
        }
    }

    // ---- exact resolution of candidates (bitwise reference sequence) ----
    const int vr0 = blk * 128 + r0, vr1 = blk * 128 + r1;
    const float* xin0 = x + (size_t)(vr0 >> 10) * 65536 + (vr0 & 1023);
    const float* xin1 = x + (size_t)(vr1 >> 10) * 65536 + (vr1 & 1023);
    u64 best0 = ~0ull, best1 = ~0ull;
    if (cnt <= 8) {
        for (int i = 0; i < cnt; i++) {
            const u32 ent = myCand[i];
            const int k = (int)(ent >> 1);
            if (ent & 1) {
                const u64 p = packdk(exact_dist(xin1, w, k, xn1, sEN[k]), k);
                if (p < best1) best1 = p;
            } else {
                const u64 p = packdk(exact_dist(xin0, w, k, xn0, sEN[k]), k);
                if (p < best0) best0 = p;
            }
        }
    } else {   // overflow (astronomically rare): exact scan of this thread's subset
        for (int i = 0; i < 128; i++)
#pragma unroll
            for (int i2 = 0; i2 < 2; i2++) {
                const int k = i * 8 + 2 * t4 + i2;
                const u64 p0 = packdk(exact_dist(xin0, w, k, xn0, sEN[k]), k);
                const u64 p1 = packdk(exact_dist(xin1, w, k, xn1, sEN[k]), k);
                if (p0 < best0) best0 = p0;
                if (p1 < best1) best1 = p1;
            }
    }
#pragma unroll
    for (int m = 1; m <= 2; m <<= 1) {
        const u64 o0 = __shfl_xor_sync(0xffffffffu, best0, m);
        const u64 o1 = __shfl_xor_sync(0xffffffffu, best1, m);
        if (o0 < best0) best0 = o0;
        if (o1 < best1) best1 = o1;
    }
    if (t4 == 0) {
        sBest[r0] = (int)(best0 & 0xffffffffu);
        sBest[r1] = (int)(best1 & 0xffffffffu);
    }
    __syncthreads();

    // ---- fused epilogue: STE quantized + loss + counts + one-hot '1' fixup ----
    if (tid < 128) {
        const int v  = blk * 128 + tid;
        const int kk = sBest[tid];
        const float* eb  = w + (size_t)kk * DIM;
        const float* xin = x + (size_t)(v >> 10) * 65536 + (v & 1023);
        float*       q   = out + OFF_Q + (size_t)(v >> 10) * 65536 + (v & 1023);
        float diff2 = 0.f;
#pragma unroll
        for (int d = 0; d < DIM; d++) {
            const float xv = xin[(size_t)d * 1024];
            const float df = __fsub_rn(eb[d], xv);
            diff2 = fmaf(df, df, diff2);
            q[(size_t)d * 1024] = __fadd_rn(xv, df);
        }
        atomicAdd(&g_counts[kk], 1);
        sRed[tid] = diff2;
        out[OFF_ENC + (size_t)v * 1024 + kk] = 1.0f;   // zeros streamed earlier
    }
    __syncthreads();
#pragma unroll
    for (int s = 64; s > 0; s >>= 1) {
        if (tid < s) sRed[tid] += sRed[tid + s];
        __syncthreads();
    }
    if (tid == 0) g_partial[blk] = sRed[0];
}

// -------- finalize: loss scalar + perplexity --------
__global__ void vq_finalize(float* __restrict__ out) {
    __shared__ float sh[512];
    const int t = threadIdx.x;

    sh[t] = g_partial[t];
    __syncthreads();
#pragma unroll
    for (int s = 256; s > 0; s >>= 1) {
        if (t < s) sh[t] += sh[t + s];
        __syncthreads();
    }
    if (t == 0) out[0] = 0.25f * sh[0] / 4194304.0f;
    __syncthreads();

    float term = 0.f;
#pragma unroll
    for (int k = t; k < KCODE; k += 512) {
        const float p = (float)g_counts[k] * (1.0f / 65536.0f);
        term += p * logf(p + 1e-10f);
    }
    sh[t] = term;
    __syncthreads();
#pragma unroll
    for (int s = 256; s > 0; s >>= 1) {
        if (t < s) sh[t] += sh[t + s];
        __syncthreads();
    }
    if (t == 0) out[OFF_PERP] = expf(-sh[0]);
}

extern "C" void kernel_launch(void* const* d_in, const int* in_sizes, int n_in,
                              void* d_out, int out_size) {
    const float* x = (const float*)d_in[0];   // [64,64,32,32] f32 NCHW
    const float* w = (const float*)d_in[1];   // [1024,64] f32
    float* out = (float*)d_out;

    cudaFuncSetAttribute(vq_mma, cudaFuncAttributeMaxDynamicSharedMemorySize, 65024);

    vq_prep<<<32, 32>>>(w);
    vq_mma<<<512, 256, 65024>>>(x, w, out);
    vq_finalize<<<1, 512>>>(out);
}